// round 11
// baseline (speedup 1.0000x reference)
#include <cuda_runtime.h>
#include <cuda_bf16.h>

#define NN 64
#define SS 512
#define DD 512
#define CC 1024
#define GRID 128
#define NTHREADS 256

// ---------------- device scratch (static, no allocations) ----------------
__device__ float g_X[(size_t)NN * SS * DD];   // LN'd masked inputs (64 MB)
__device__ float g_ht[NN * DD];
__device__ float g_gs[NN * DD];
__device__ float g_inter[NN * CC];
__device__ float g_cont[NN * 4 * DD];
__device__ unsigned g_cnt;
__device__ unsigned g_sense;

typedef unsigned long long ull;

__device__ __forceinline__ void fma2(ull& d, ull a, ull b) {
    asm("fma.rn.f32x2 %0, %1, %2, %0;" : "+l"(d) : "l"(a), "l"(b));
}
__device__ __forceinline__ ull dup2(float f) {
    ull r; asm("mov.b64 %0, {%1, %1};" : "=l"(r) : "f"(f)); return r;
}
__device__ __forceinline__ float2 unp(ull v) {
    float2 r; asm("mov.b64 {%0, %1}, %2;" : "=f"(r.x), "=f"(r.y) : "l"(v)); return r;
}
__device__ __forceinline__ float sigm(float x) { return 1.f / (1.f + expf(-x)); }
__device__ __forceinline__ float gelu_t(float x) {
    float u = x + 0.044715f * x * x * x;
    return 0.5f * x * (1.f + tanhf(0.7978845608028654f * u));
}

// =================== kernel 1: g_X = (seq*mask) @ W_init + b_init ===================
__global__ void __launch_bounds__(256) k_init_gemm(
    const float* __restrict__ seq, const float* __restrict__ mask,
    const float* __restrict__ Wi, const float* __restrict__ bi)
{
    __shared__ float As[16][64];
    __shared__ float Bs[16][64];
    const int tid = threadIdx.x;
    const int row0 = blockIdx.y * 64;     // rows = n*S + s
    const int n0 = blockIdx.x * 64;
    const int lm = tid >> 2;              // row for A-load (0..63)
    const int kq = (tid & 3) * 4;         // k-quad for A-load
    const int bk = tid >> 4;              // k for B-load (0..15)
    const int bn = (tid & 15) * 4;        // n-quad for B-load
    const int ty = tid >> 4;              // m-group for compute
    const int tx = tid & 15;              // n-group for compute
    const float mval = mask[row0 + lm];

    float acc[4][4];
#pragma unroll
    for (int i = 0; i < 4; i++)
#pragma unroll
        for (int j = 0; j < 4; j++) acc[i][j] = 0.f;

    for (int kt = 0; kt < DD / 16; kt++) {
        float4 a = *(const float4*)&seq[(size_t)(row0 + lm) * DD + kt * 16 + kq];
        As[kq + 0][lm] = a.x * mval;
        As[kq + 1][lm] = a.y * mval;
        As[kq + 2][lm] = a.z * mval;
        As[kq + 3][lm] = a.w * mval;
        *(float4*)&Bs[bk][bn] = *(const float4*)&Wi[(size_t)(kt * 16 + bk) * DD + n0 + bn];
        __syncthreads();
#pragma unroll
        for (int k = 0; k < 16; k++) {
            float4 av = *(const float4*)&As[k][ty * 4];
            float4 bv = *(const float4*)&Bs[k][tx * 4];
            float am[4] = {av.x, av.y, av.z, av.w};
            float bb[4] = {bv.x, bv.y, bv.z, bv.w};
#pragma unroll
            for (int i = 0; i < 4; i++)
#pragma unroll
                for (int j = 0; j < 4; j++) acc[i][j] += am[i] * bb[j];
        }
        __syncthreads();
    }
#pragma unroll
    for (int i = 0; i < 4; i++)
#pragma unroll
        for (int j = 0; j < 4; j++) {
            int n = n0 + tx * 4 + j;
            g_X[(size_t)(row0 + ty * 4 + i) * DD + n] = acc[i][j] + bi[n];
        }
}

// ============ kernel 2: in-place LN rows of g_X, * mask; reset barrier ============
__global__ void __launch_bounds__(128) k_ln(
    const float* __restrict__ lng, const float* __restrict__ lnb,
    const float* __restrict__ mask)
{
    if (blockIdx.x == 0 && threadIdx.x == 0) { g_cnt = 0; g_sense = 0; }
    const int row = blockIdx.x;           // n*S + s
    const int tid = threadIdx.x;
    float* xp = g_X + (size_t)row * DD;
    float4 v = *(float4*)(xp + tid * 4);
    __shared__ float sc[16];

    float s = v.x + v.y + v.z + v.w;
#pragma unroll
    for (int o = 16; o; o >>= 1) s += __shfl_xor_sync(0xffffffffu, s, o);
    if ((tid & 31) == 0) sc[tid >> 5] = s;
    __syncthreads();
    if (tid == 0) sc[8] = (sc[0] + sc[1] + sc[2] + sc[3]) * (1.f / DD);
    __syncthreads();
    float m = sc[8];

    float a0 = v.x - m, a1 = v.y - m, a2 = v.z - m, a3 = v.w - m;
    float q = a0 * a0 + a1 * a1 + a2 * a2 + a3 * a3;
#pragma unroll
    for (int o = 16; o; o >>= 1) q += __shfl_xor_sync(0xffffffffu, q, o);
    if ((tid & 31) == 0) sc[tid >> 5] = q;
    __syncthreads();
    if (tid == 0) sc[9] = rsqrtf((sc[0] + sc[1] + sc[2] + sc[3]) * (1.f / DD) + 1e-5f);
    __syncthreads();
    float rs = sc[9];

    float mval = mask[row];
    float4 g4 = *(const float4*)(lng + tid * 4);
    float4 b4 = *(const float4*)(lnb + tid * 4);
    v.x = (a0 * rs * g4.x + b4.x) * mval;
    v.y = (a1 * rs * g4.y + b4.y) * mval;
    v.z = (a2 * rs * g4.z + b4.z) * mval;
    v.w = (a3 * rs * g4.w + b4.w) * mval;
    *(float4*)(xp + tid * 4) = v;
}

// =================== persistent recurrence kernel ===================
__device__ __forceinline__ void gbar(unsigned* barc) {
    __threadfence();
    __syncthreads();
    unsigned target = ++(*barc);
    if (threadIdx.x == 0) {
        unsigned v = atomicAdd(&g_cnt, 1u);
        if (v == GRID - 1) {
            g_cnt = 0;
            __threadfence();
            atomicExch(&g_sense, target);
        } else {
            while (*(volatile unsigned*)&g_sense < target) { }
        }
    }
    __syncthreads();
    __threadfence();
}

// block sum over 256 threads (8 warps)
__device__ __forceinline__ float bsum(float v, float* sc) {
    int lane = threadIdx.x & 31, w = threadIdx.x >> 5;
#pragma unroll
    for (int o = 16; o; o >>= 1) v += __shfl_xor_sync(0xffffffffu, v, o);
    if (lane == 0) sc[w] = v;
    __syncthreads();
    if (w == 0) {
        float s = (lane < 8) ? sc[lane] : 0.f;
#pragma unroll
        for (int o = 4; o; o >>= 1) s += __shfl_xor_sync(0xffffffffu, s, o);
        if (lane == 0) sc[8] = s;
    }
    __syncthreads();
    float r = sc[8];
    __syncthreads();
    return r;
}

__global__ void __launch_bounds__(NTHREADS, 1) k_recur(
    const float* __restrict__ mask, const float* __restrict__ START,
    const float* __restrict__ W1, const float* __restrict__ b1,
    const float* __restrict__ W2, const float* __restrict__ b2,
    const float* __restrict__ lng, const float* __restrict__ lnb,
    float* __restrict__ out)
{
    // per-warp staging: 8 kk x 64 m duplicated f32x2 (4 KB/warp, 32 KB total)
    // after each warp's k-loop, its slot is reused for its fp32 partials.
    __shared__ ull A2[8][512];
    __shared__ float scC[16];

    const int tid = threadIdx.x;
    const int lane = tid & 31;
    const int warp = tid >> 5;
    const int b = blockIdx.x;
    const int mg = lane & 15;
    const int ng = lane >> 4;
    const int m0 = mg * 4;
    const int k0 = warp * 128;
    ull* const Aw = &A2[warp][0];
    float* const Rw = (float*)Aw;          // this warp's 1024-float partial slot
    float* const Rall = (float*)A2;
    unsigned barc = 0;

    // init carry
    if (b < NN) {
#pragma unroll
        for (int j = 0; j < 2; j++) {
            int d = tid + 256 * j;
            float s = START[d];
            g_ht[b * DD + d] = s;
            g_gs[b * DD + d] = s;
        }
    }
    gbar(&barc);

    const int nA0 = b * 8;
    const int nB0 = b * 16;

    for (int t = 0; t < SS; t++) {
        // ---------- phase A: inter = gelu(cat @ W1 + b1); block owns 8 cols ----------
        {
            ull acc[4][2];
#pragma unroll
            for (int i = 0; i < 4; i++) { acc[i][0] = 0; acc[i][1] = 0; }

            for (int kc = 0; kc < 16; kc++) {
                const int kb = k0 + kc * 8;
                const float *src0, *src1;
                if (warp < 4) {
                    src0 = g_ht + (size_t)lane * DD + kb;
                    src1 = g_ht + (size_t)(lane + 32) * DD + kb;
                } else {
                    size_t off = (size_t)t * DD + (kb - 512);
                    src0 = g_X + (size_t)lane * SS * DD + off;
                    src1 = g_X + (size_t)(lane + 32) * SS * DD + off;
                }
                float4 a0 = __ldcg((const float4*)src0);
                float4 a1 = __ldcg((const float4*)(src0 + 4));
                float4 a2 = __ldcg((const float4*)src1);
                float4 a3 = __ldcg((const float4*)(src1 + 4));
                __syncwarp();
                const int m2 = lane + 32;
                Aw[0 * 64 + lane] = dup2(a0.x); Aw[1 * 64 + lane] = dup2(a0.y);
                Aw[2 * 64 + lane] = dup2(a0.z); Aw[3 * 64 + lane] = dup2(a0.w);
                Aw[4 * 64 + lane] = dup2(a1.x); Aw[5 * 64 + lane] = dup2(a1.y);
                Aw[6 * 64 + lane] = dup2(a1.z); Aw[7 * 64 + lane] = dup2(a1.w);
                Aw[0 * 64 + m2] = dup2(a2.x);   Aw[1 * 64 + m2] = dup2(a2.y);
                Aw[2 * 64 + m2] = dup2(a2.z);   Aw[3 * 64 + m2] = dup2(a2.w);
                Aw[4 * 64 + m2] = dup2(a3.x);   Aw[5 * 64 + m2] = dup2(a3.y);
                Aw[6 * 64 + m2] = dup2(a3.z);   Aw[7 * 64 + m2] = dup2(a3.w);
                __syncwarp();
                const float* wrow = W1 + (size_t)kb * CC + nA0 + ng * 4;
#pragma unroll
                for (int kk = 0; kk < 8; kk++) {
                    ulonglong2 pa = *(const ulonglong2*)(Aw + kk * 64 + m0);
                    ulonglong2 pb = *(const ulonglong2*)(Aw + kk * 64 + m0 + 2);
                    ulonglong2 w  = *(const ulonglong2*)(wrow + (size_t)kk * CC);
                    fma2(acc[0][0], pa.x, w.x); fma2(acc[0][1], pa.x, w.y);
                    fma2(acc[1][0], pa.y, w.x); fma2(acc[1][1], pa.y, w.y);
                    fma2(acc[2][0], pb.x, w.x); fma2(acc[2][1], pb.x, w.y);
                    fma2(acc[3][0], pb.y, w.x); fma2(acc[3][1], pb.y, w.y);
                }
            }
            __syncwarp();   // all lanes done reading Aw before partials overwrite it
#pragma unroll
            for (int mi = 0; mi < 4; mi++)
#pragma unroll
                for (int p = 0; p < 2; p++) {
                    float2 f = unp(acc[mi][p]);
                    int idx = (m0 + mi) * 8 + ng * 4 + p * 2;
                    Rw[idx] = f.x; Rw[idx + 1] = f.y;
                }
            __syncthreads();
#pragma unroll
            for (int j = 0; j < 2; j++) {
                int idx = tid + 256 * j;
                int m = idx >> 3, nl = idx & 7;
                float s = b1[nA0 + nl];
#pragma unroll
                for (int w = 0; w < 8; w++) s += Rall[w * 1024 + idx];
                g_inter[m * CC + nA0 + nl] = gelu_t(s);
            }
        }
        gbar(&barc);

        // ---------- phase B: cont = inter @ W2 + b2; block owns 16 cols ----------
        {
            ull acc[4][4];
#pragma unroll
            for (int i = 0; i < 4; i++)
#pragma unroll
                for (int j = 0; j < 4; j++) acc[i][j] = 0;

            for (int kc = 0; kc < 16; kc++) {
                const int kb = k0 + kc * 8;
                const float* src0 = g_inter + (size_t)lane * CC + kb;
                const float* src1 = g_inter + (size_t)(lane + 32) * CC + kb;
                float4 a0 = __ldcg((const float4*)src0);
                float4 a1 = __ldcg((const float4*)(src0 + 4));
                float4 a2 = __ldcg((const float4*)src1);
                float4 a3 = __ldcg((const float4*)(src1 + 4));
                __syncwarp();
                const int m2 = lane + 32;
                Aw[0 * 64 + lane] = dup2(a0.x); Aw[1 * 64 + lane] = dup2(a0.y);
                Aw[2 * 64 + lane] = dup2(a0.z); Aw[3 * 64 + lane] = dup2(a0.w);
                Aw[4 * 64 + lane] = dup2(a1.x); Aw[5 * 64 + lane] = dup2(a1.y);
                Aw[6 * 64 + lane] = dup2(a1.z); Aw[7 * 64 + lane] = dup2(a1.w);
                Aw[0 * 64 + m2] = dup2(a2.x);   Aw[1 * 64 + m2] = dup2(a2.y);
                Aw[2 * 64 + m2] = dup2(a2.z);   Aw[3 * 64 + m2] = dup2(a2.w);
                Aw[4 * 64 + m2] = dup2(a3.x);   Aw[5 * 64 + m2] = dup2(a3.y);
                Aw[6 * 64 + m2] = dup2(a3.z);   Aw[7 * 64 + m2] = dup2(a3.w);
                __syncwarp();
                const float* wrow = W2 + (size_t)kb * (4 * DD) + nB0 + ng * 8;
#pragma unroll
                for (int kk = 0; kk < 8; kk++) {
                    ulonglong2 pa = *(const ulonglong2*)(Aw + kk * 64 + m0);
                    ulonglong2 pb = *(const ulonglong2*)(Aw + kk * 64 + m0 + 2);
                    const float* wr = wrow + (size_t)kk * (4 * DD);
                    ulonglong2 w0 = *(const ulonglong2*)(wr);
                    ulonglong2 w1 = *(const ulonglong2*)(wr + 4);
                    ull av[4] = {pa.x, pa.y, pb.x, pb.y};
#pragma unroll
                    for (int mi = 0; mi < 4; mi++) {
                        fma2(acc[mi][0], av[mi], w0.x);
                        fma2(acc[mi][1], av[mi], w0.y);
                        fma2(acc[mi][2], av[mi], w1.x);
                        fma2(acc[mi][3], av[mi], w1.y);
                    }
                }
            }
            __syncwarp();
#pragma unroll
            for (int mi = 0; mi < 4; mi++)
#pragma unroll
                for (int np = 0; np < 4; np++) {
                    float2 f = unp(acc[mi][np]);
                    int idx = (m0 + mi) * 16 + ng * 8 + np * 2;
                    Rw[idx] = f.x; Rw[idx + 1] = f.y;
                }
            __syncthreads();
#pragma unroll
            for (int j = 0; j < 4; j++) {
                int idx = tid + 256 * j;
                int m = idx >> 4, nl = idx & 15;
                float s = b2[nB0 + nl];
#pragma unroll
                for (int w = 0; w < 8; w++) s += Rall[w * 1024 + idx];
                g_cont[m * (4 * DD) + nB0 + nl] = s;
            }
        }
        gbar(&barc);

        // ---------- phase C: gates + LN + state update (blocks 0..63) ----------
        if (b < NN) {
            float mval = mask[(size_t)b * SS + t];
            float vv[2];
#pragma unroll
            for (int h = 0; h < 2; h++) {
                int d = tid + 256 * h;
                const float* cb = g_cont + b * (4 * DD);
                float c0 = __ldcg(cb + d);
                float c1 = __ldcg(cb + 512 + d);
                float c2 = __ldcg(cb + 1024 + d);
                float c3 = __ldcg(cb + 1536 + d);
                float h0 = g_ht[b * DD + d];
                float x0 = g_X[((size_t)b * SS + t) * DD + d];
                vv[h] = sigm(c0) * h0 + sigm(c1) * x0 + sigm(c2) * c3;
            }
            float mean = bsum(vv[0] + vv[1], scC) * (1.f / DD);
            float e0 = vv[0] - mean, e1 = vv[1] - mean;
            float var = bsum(e0 * e0 + e1 * e1, scC) * (1.f / DD);
            float rs = rsqrtf(var + 1e-5f);
#pragma unroll
            for (int h = 0; h < 2; h++) {
                int d = tid + 256 * h;
                float hn = (vv[h] - mean) * rs * lng[d] + lnb[d];
                g_ht[b * DD + d] = hn;
                out[((size_t)b * SS + t) * DD + d] = hn * mval;
                g_gs[b * DD + d] = mval * hn + (1.f - mval) * g_gs[b * DD + d];
            }
        }
        gbar(&barc);
    }

    // final global_state
    if (b < NN) {
#pragma unroll
        for (int h = 0; h < 2; h++) {
            int d = tid + 256 * h;
            out[(size_t)NN * SS * DD + b * DD + d] = g_gs[b * DD + d];
        }
    }
}

extern "C" void kernel_launch(void* const* d_in, const int* in_sizes, int n_in,
                              void* d_out, int out_size) {
    (void)in_sizes; (void)n_in; (void)out_size;
    const float* seq   = (const float*)d_in[0];
    const float* mask  = (const float*)d_in[1];
    const float* START = (const float*)d_in[2];
    const float* Wi    = (const float*)d_in[3];
    const float* bi    = (const float*)d_in[4];
    const float* W1    = (const float*)d_in[5];
    const float* b1    = (const float*)d_in[6];
    const float* W2    = (const float*)d_in[7];
    const float* b2    = (const float*)d_in[8];
    const float* lng   = (const float*)d_in[9];
    const float* lnb   = (const float*)d_in[10];
    float* out = (float*)d_out;

    dim3 g1(DD / 64, (NN * SS) / 64);
    k_init_gemm<<<g1, 256>>>(seq, mask, Wi, bi);
    k_ln<<<NN * SS, 128>>>(lng, lnb, mask);
    k_recur<<<GRID, NTHREADS>>>(mask, START, W1, b1, W2, b2, lng, lnb, out);
}